// round 2
// baseline (speedup 1.0000x reference)
#include <cuda_runtime.h>
#include <math.h>

#define B_   8192
#define T_   10
#define F_   561
#define H_   256
#define O_   12
#define G4H  (4 * H_)           // 1024
#define NBT  (B_ * T_)          // 81920

// ---------------- scratch (static device memory; no allocations) ----------------
__device__ float g_xp[NBT * H_];          // [B*T, H]   input projection
__device__ float g_pre0[(size_t)NBT * G4H]; // [B*T, 4H]  precomputed x-part of layer0 gates (+biases)
__device__ float g_gates[B_ * G4H];       // [B, 4H]    per-step gate scratch
__device__ float g_h0[B_ * H_];
__device__ float g_c0[B_ * H_];
__device__ float g_h1[B_ * H_];
__device__ float g_c1[B_ * H_];
__device__ float g_hs[NBT * H_];          // [B*T, H]   layer1 hidden per step

// ---------------- zero init of recurrent state ----------------
__global__ void zero_state_kernel() {
    int n = B_ * H_;
    for (int i = blockIdx.x * blockDim.x + threadIdx.x; i < n; i += gridDim.x * blockDim.x) {
        g_h0[i] = 0.f; g_c0[i] = 0.f; g_h1[i] = 0.f; g_c1[i] = 0.f;
    }
}

// ---------------- generic SGEMM: C = [Cin] + [bias1] + [bias2] + A1*B1^T + [A2*B2^T] ----------------
// A: [M,K] row-major;  Bw: [N,K] row-major (so we multiply by its transpose);  C: [M,N]
#define BM 128
#define BN 64
#define BK 8
#define TM 8
#define TN 4
// threads = (BM/TM)*(BN/TN) = 16*16 = 256

__global__ __launch_bounds__(256)
void gemm_kernel(const float* __restrict__ A1, const float* __restrict__ B1, int K1,
                 const float* __restrict__ A2, const float* __restrict__ B2, int K2,
                 const float* __restrict__ Cin, int ldcin,
                 const float* __restrict__ bias1, const float* __restrict__ bias2,
                 float* __restrict__ C, int M, int N)
{
    __shared__ float As[BK][BM + 1];
    __shared__ float Bs[BK][BN + 1];

    const int tid = threadIdx.x;
    const int tx = tid % 16;          // N direction
    const int ty = tid / 16;          // M direction
    const int rowBase = blockIdx.y * BM;
    const int colBase = blockIdx.x * BN;

    float acc[TM][TN];
#pragma unroll
    for (int i = 0; i < TM; i++)
#pragma unroll
        for (int j = 0; j < TN; j++) acc[i][j] = 0.f;

#pragma unroll 1
    for (int src = 0; src < 2; ++src) {
        const float* A  = (src == 0) ? A1 : A2;
        const float* Bw = (src == 0) ? B1 : B2;
        const int    K  = (src == 0) ? K1 : K2;
        if (A == nullptr) continue;

        for (int k0 = 0; k0 < K; k0 += BK) {
            // load A tile: BM x BK = 1024 elems, 4 per thread
#pragma unroll
            for (int l = 0; l < 4; l++) {
                int idx = tid + 256 * l;
                int k = idx % BK;
                int m = idx / BK;
                int gr = rowBase + m;
                int gk = k0 + k;
                float v = 0.f;
                if (gr < M && gk < K) v = A[(size_t)gr * K + gk];
                As[k][m] = v;
            }
            // load B tile: BN x BK = 512 elems, 2 per thread
#pragma unroll
            for (int l = 0; l < 2; l++) {
                int idx = tid + 256 * l;
                int k = idx % BK;
                int n = idx / BK;
                int gn = colBase + n;
                int gk = k0 + k;
                float v = 0.f;
                if (gn < N && gk < K) v = Bw[(size_t)gn * K + gk];
                Bs[k][n] = v;
            }
            __syncthreads();

#pragma unroll
            for (int kk = 0; kk < BK; kk++) {
                float a[TM], b[TN];
#pragma unroll
                for (int i = 0; i < TM; i++) a[i] = As[kk][ty * TM + i];
#pragma unroll
                for (int j = 0; j < TN; j++) b[j] = Bs[kk][tx * TN + j];
#pragma unroll
                for (int i = 0; i < TM; i++)
#pragma unroll
                    for (int j = 0; j < TN; j++) acc[i][j] = fmaf(a[i], b[j], acc[i][j]);
            }
            __syncthreads();
        }
    }

    // epilogue
#pragma unroll
    for (int i = 0; i < TM; i++) {
        int row = rowBase + ty * TM + i;
        if (row >= M) continue;
#pragma unroll
        for (int j = 0; j < TN; j++) {
            int col = colBase + tx * TN + j;
            if (col >= N) continue;
            float v = acc[i][j];
            if (Cin)   v += Cin[(size_t)row * ldcin + col];
            if (bias1) v += bias1[col];
            if (bias2) v += bias2[col];
            C[(size_t)row * N + col] = v;
        }
    }
}

// ---------------- LSTM pointwise ----------------
__device__ __forceinline__ float sigmoidf_(float x) { return 1.0f / (1.0f + expf(-x)); }

__global__ __launch_bounds__(256)
void lstm_pointwise(const float* __restrict__ gates,
                    float* __restrict__ h, float* __restrict__ c,
                    float* __restrict__ hs, int t,
                    float* __restrict__ hn_out, float* __restrict__ cn_out)
{
    int idx = blockIdx.x * blockDim.x + threadIdx.x;    // b*H + j
    if (idx >= B_ * H_) return;
    int b = idx / H_;
    int j = idx % H_;
    const float* g = gates + (size_t)b * G4H;
    float gi = g[j];
    float gf = g[j + H_];
    float gg = g[j + 2 * H_];
    float go = g[j + 3 * H_];
    float c_new = sigmoidf_(gf) * c[idx] + sigmoidf_(gi) * tanhf(gg);
    float h_new = sigmoidf_(go) * tanhf(c_new);
    c[idx] = c_new;
    h[idx] = h_new;
    if (hs) hs[((size_t)b * T_ + t) * H_ + j] = h_new;
    if (hn_out) { hn_out[idx] = h_new; cn_out[idx] = c_new; }
}

// ---------------- output projection: out[r, o] = hs[r,:] . W_out[o,:] + b_out[o] ----------------
// one warp per row; 8 rows per block
__global__ __launch_bounds__(256)
void proj_kernel(const float* __restrict__ hs, const float* __restrict__ W_out,
                 const float* __restrict__ b_out, float* __restrict__ out)
{
    __shared__ float Ws[O_ * H_];       // 12*256 floats = 12 KB
    __shared__ float bs[O_];
    for (int i = threadIdx.x; i < O_ * H_; i += blockDim.x) Ws[i] = W_out[i];
    if (threadIdx.x < O_) bs[threadIdx.x] = b_out[threadIdx.x];
    __syncthreads();

    int warp = threadIdx.x / 32;
    int lane = threadIdx.x % 32;
    int row = blockIdx.x * 8 + warp;
    if (row >= NBT) return;

    float x[H_ / 32];
#pragma unroll
    for (int j = 0; j < H_ / 32; j++) x[j] = hs[(size_t)row * H_ + lane + 32 * j];

#pragma unroll
    for (int o = 0; o < O_; o++) {
        float s = 0.f;
#pragma unroll
        for (int j = 0; j < H_ / 32; j++) s = fmaf(x[j], Ws[o * H_ + lane + 32 * j], s);
#pragma unroll
        for (int off = 16; off > 0; off >>= 1) s += __shfl_xor_sync(0xffffffffu, s, off);
        if (lane == 0) out[(size_t)row * O_ + o] = s + bs[o];
    }
}

// ---------------- launch ----------------
extern "C" void kernel_launch(void* const* d_in, const int* in_sizes, int n_in,
                              void* d_out, int out_size)
{
    const float* X     = (const float*)d_in[0];   // [B,T,F]
    const float* W_inp = (const float*)d_in[1];   // [H,F]
    const float* b_inp = (const float*)d_in[2];   // [H]
    const float* Wih0  = (const float*)d_in[3];   // [4H,H]
    const float* Whh0  = (const float*)d_in[4];
    const float* bih0  = (const float*)d_in[5];
    const float* bhh0  = (const float*)d_in[6];
    const float* Wih1  = (const float*)d_in[7];
    const float* Whh1  = (const float*)d_in[8];
    const float* bih1  = (const float*)d_in[9];
    const float* bhh1  = (const float*)d_in[10];
    const float* W_out = (const float*)d_in[11];  // [O,H]
    const float* b_out = (const float*)d_in[12];

    float* out     = (float*)d_out;                      // [B,T,O]
    float* hn_base = out + (size_t)B_ * T_ * O_;         // [2,B,H]
    float* cn_base = hn_base + (size_t)2 * B_ * H_;      // [2,B,H]

    static float *xp = nullptr, *pre0, *gates, *h0, *c0, *h1, *c1, *hs;
    if (!xp) {
        cudaGetSymbolAddress((void**)&xp,    g_xp);
        cudaGetSymbolAddress((void**)&pre0,  g_pre0);
        cudaGetSymbolAddress((void**)&gates, g_gates);
        cudaGetSymbolAddress((void**)&h0,    g_h0);
        cudaGetSymbolAddress((void**)&c0,    g_c0);
        cudaGetSymbolAddress((void**)&h1,    g_h1);
        cudaGetSymbolAddress((void**)&c1,    g_c1);
        cudaGetSymbolAddress((void**)&hs,    g_hs);
    }

    // 1) zero recurrent state
    zero_state_kernel<<<1024, 256>>>();

    // 2) xp = X @ W_inp^T + b_inp        [NBT, H]
    {
        dim3 grid(H_ / BN, NBT / BM);
        gemm_kernel<<<grid, 256>>>(X, W_inp, F_, nullptr, nullptr, 0,
                                   nullptr, 0, b_inp, nullptr, xp, NBT, H_);
    }
    // 3) pre0 = xp @ Wih0^T + bih0 + bhh0   [NBT, 4H]
    {
        dim3 grid(G4H / BN, NBT / BM);
        gemm_kernel<<<grid, 256>>>(xp, Wih0, H_, nullptr, nullptr, 0,
                                   nullptr, 0, bih0, bhh0, pre0, NBT, G4H);
    }

    // 4) recurrence
    for (int t = 0; t < T_; t++) {
        bool last = (t == T_ - 1);
        // layer0 gates: gates = pre0[:,t,:] + h0 @ Whh0^T
        {
            dim3 grid(G4H / BN, B_ / BM);
            gemm_kernel<<<grid, 256>>>(h0, Whh0, H_, nullptr, nullptr, 0,
                                       pre0 + (size_t)t * G4H, T_ * G4H,
                                       nullptr, nullptr, gates, B_, G4H);
        }
        lstm_pointwise<<<(B_ * H_) / 256, 256>>>(gates, h0, c0, nullptr, t,
                                                 last ? hn_base : nullptr,
                                                 last ? cn_base : nullptr);
        // layer1 gates: gates = bih1 + bhh1 + h0 @ Wih1^T + h1 @ Whh1^T
        {
            dim3 grid(G4H / BN, B_ / BM);
            gemm_kernel<<<grid, 256>>>(h0, Wih1, H_, h1, Whh1, H_,
                                       nullptr, 0, bih1, bhh1, gates, B_, G4H);
        }
        lstm_pointwise<<<(B_ * H_) / 256, 256>>>(gates, h1, c1, hs, t,
                                                 last ? hn_base + (size_t)B_ * H_ : nullptr,
                                                 last ? cn_base + (size_t)B_ * H_ : nullptr);
    }

    // 5) outputs = hs @ W_out^T + b_out
    proj_kernel<<<NBT / 8, 256>>>(hs, W_out, b_out, out);
}

// round 6
// speedup vs baseline: 2.8067x; 2.8067x over previous
#include <cuda_runtime.h>
#include <cuda_bf16.h>
#include <cstdint>
#include <math.h>

#define B_   8192
#define T_   10
#define F_   561
#define H_   256
#define O_   12
#define G4H  1024
#define NBT  (B_ * T_)          // 81920
#define KX   1728               // 3*561=1683 padded up to multiple of 64
#define K3H  768                // 3*256
#define K6H  1536               // 6*256

#define SWZ128(off) ((off) ^ (((off) >> 3) & 0x70))

__device__ __forceinline__ uint32_t smem_u32(const void* p) {
    uint32_t a;
    asm("{ .reg .u64 t; cvta.to.shared.u64 t, %1; cvt.u32.u64 %0, t; }" : "=r"(a) : "l"(p));
    return a;
}

__device__ __forceinline__ void ldsm_x4(uint32_t* r, uint32_t addr) {
    asm volatile("ldmatrix.sync.aligned.m8n8.x4.shared.b16 {%0,%1,%2,%3}, [%4];"
                 : "=r"(r[0]), "=r"(r[1]), "=r"(r[2]), "=r"(r[3]) : "r"(addr));
}

__device__ __forceinline__ void mma_bf16(float* d, const uint32_t* a, uint32_t b0, uint32_t b1) {
    asm volatile("mma.sync.aligned.m16n8k16.row.col.f32.bf16.bf16.f32 "
                 "{%0,%1,%2,%3}, {%4,%5,%6,%7}, {%8,%9}, {%0,%1,%2,%3};"
                 : "+f"(d[0]), "+f"(d[1]), "+f"(d[2]), "+f"(d[3])
                 : "r"(a[0]), "r"(a[1]), "r"(a[2]), "r"(a[3]), "r"(b0), "r"(b1));
}

// ======================= scratch (static device memory) =======================
__device__ __nv_bfloat16 g_Xsplit[(size_t)NBT * KX];      // [NBT,1728] = [x_hi | x_hi | x_lo | pad]
__device__ __nv_bfloat16 g_Axp[(size_t)NBT * K3H];        // [NBT,768]  = [xp_hi | xp_hi | xp_lo]
__device__ float         g_xp[(size_t)NBT * H_];
__device__ float         g_pre0[(size_t)NBT * G4H];
__device__ float         g_gates[(size_t)B_ * G4H];
__device__ __nv_bfloat16 g_Act[(size_t)B_ * K6H];         // [B,1536]: [h0hi,h0hi,h0lo, h1hi,h1hi,h1lo]
__device__ float         g_c0[B_ * H_];
__device__ float         g_c1[B_ * H_];
__device__ float         g_hs[(size_t)NBT * H_];
__device__ __nv_bfloat16 g_WbInp[(size_t)H_ * KX];        // [256,1728] = [Whi | Wlo | Whi | pad]
__device__ __nv_bfloat16 g_Wbih0[(size_t)G4H * K3H];
__device__ __nv_bfloat16 g_Wbhh0[(size_t)G4H * K3H];
__device__ __nv_bfloat16 g_Wb1[(size_t)G4H * K6H];        // [Wih1 hi,lo,hi | Whh1 hi,lo,hi]

// ======================= mma.sync GEMM: C = [Cin] + [b1] + [b2] + A @ Bw^T =======================
// A [M,K] bf16 row-major; Bw [N,K] bf16 row-major. CTA tile 128x128, K chunk 64.
// 8 warps: 4 along M x 2 along N; warp tile 32x64; mma m16n8k16.
#define TM_ 128
#define TN_ 128
#define KC  64

#define SM_A0  0
#define SM_A1  16384
#define SM_B0  32768
#define SM_B1  49152
#define SM_TOTAL 65536

__global__ void __launch_bounds__(256)
tc_gemm(const __nv_bfloat16* __restrict__ A, long lda,
        const __nv_bfloat16* __restrict__ Bw, long ldb, int K,
        const float* __restrict__ Cin, long ldcin,
        const float* __restrict__ bias1, const float* __restrict__ bias2,
        float* __restrict__ Cout, long ldc)
{
    extern __shared__ char smem[];
    const uint32_t sb = smem_u32(smem);
    const int tid  = threadIdx.x;
    const int wid  = tid >> 5;
    const int lane = tid & 31;
    const int wm   = wid >> 1;          // 0..3  (M)
    const int wn   = wid & 1;           // 0..1  (N)
    const long rowBase = (long)blockIdx.y * TM_;
    const long colBase = (long)blockIdx.x * TN_;

    const uint32_t abuf[2] = { sb + SM_A0, sb + SM_A1 };
    const uint32_t bbuf[2] = { sb + SM_B0, sb + SM_B1 };

    float acc[2][8][4];
#pragma unroll
    for (int i = 0; i < 2; i++)
#pragma unroll
        for (int j = 0; j < 8; j++)
#pragma unroll
            for (int k = 0; k < 4; k++) acc[i][j][k] = 0.f;

    const int nch = K / KC;

#define LOAD_CHUNK(c, buf) do { \
    _Pragma("unroll") \
    for (int l = 0; l < 4; l++) { \
        int idx = tid + 256 * l; int r = idx >> 3, v = idx & 7; \
        const void* gp = A + (rowBase + r) * lda + (long)(c) * KC + v * 8; \
        uint32_t s = abuf[buf] + SWZ128(r * 128 + v * 16); \
        asm volatile("cp.async.cg.shared.global [%0], [%1], 16;\n" :: "r"(s), "l"(gp)); \
    } \
    _Pragma("unroll") \
    for (int l = 0; l < 4; l++) { \
        int idx = tid + 256 * l; int r = idx >> 3, v = idx & 7; \
        const void* gp = Bw + (colBase + r) * ldb + (long)(c) * KC + v * 8; \
        uint32_t s = bbuf[buf] + SWZ128(r * 128 + v * 16); \
        asm volatile("cp.async.cg.shared.global [%0], [%1], 16;\n" :: "r"(s), "l"(gp)); \
    } \
    asm volatile("cp.async.commit_group;\n"); \
} while (0)

    LOAD_CHUNK(0, 0);
    if (nch > 1) LOAD_CHUNK(1, 1);

    for (int c = 0; c < nch; c++) {
        const int buf = c & 1;
        if (c + 1 < nch) asm volatile("cp.async.wait_group 1;\n" ::: "memory");
        else             asm volatile("cp.async.wait_group 0;\n" ::: "memory");
        __syncthreads();

        const uint32_t As = abuf[buf];
        const uint32_t Bs = bbuf[buf];
#pragma unroll
        for (int ks = 0; ks < 4; ks++) {
            uint32_t afr[2][4];
#pragma unroll
            for (int mt = 0; mt < 2; mt++) {
                int row = wm * 32 + mt * 16 + (lane & 15);
                int kc  = ks * 16 + ((lane >> 4) << 3);
                ldsm_x4(afr[mt], As + SWZ128(row * 128 + kc * 2));
            }
            uint32_t bfr[4][4];
#pragma unroll
            for (int bt = 0; bt < 4; bt++) {
                int nr = wn * 64 + bt * 16 + (lane & 7) + ((lane >> 4) << 3);
                int kc = ks * 16 + (((lane >> 3) & 1) << 3);
                ldsm_x4(bfr[bt], Bs + SWZ128(nr * 128 + kc * 2));
            }
#pragma unroll
            for (int mt = 0; mt < 2; mt++)
#pragma unroll
                for (int nt = 0; nt < 8; nt++) {
                    const uint32_t* bp = bfr[nt >> 1];
                    if (nt & 1) mma_bf16(acc[mt][nt], afr[mt], bp[2], bp[3]);
                    else        mma_bf16(acc[mt][nt], afr[mt], bp[0], bp[1]);
                }
        }
        __syncthreads();
        if (c + 2 < nch) LOAD_CHUNK(c + 2, buf);
    }

    // epilogue: direct stores, fused Cin + biases
#pragma unroll
    for (int mt = 0; mt < 2; mt++) {
#pragma unroll
        for (int nt = 0; nt < 8; nt++) {
            long row = rowBase + wm * 32 + mt * 16 + (lane >> 2);
            long col = colBase + wn * 64 + nt * 8 + ((lane & 3) << 1);
            float2 v0 = make_float2(acc[mt][nt][0], acc[mt][nt][1]);
            float2 v1 = make_float2(acc[mt][nt][2], acc[mt][nt][3]);
            if (Cin) {
                float2 c0 = *(const float2*)&Cin[row * ldcin + col];
                float2 c1 = *(const float2*)&Cin[(row + 8) * ldcin + col];
                v0.x += c0.x; v0.y += c0.y; v1.x += c1.x; v1.y += c1.y;
            }
            if (bias1) {
                float2 b = *(const float2*)&bias1[col];
                v0.x += b.x; v0.y += b.y; v1.x += b.x; v1.y += b.y;
            }
            if (bias2) {
                float2 b = *(const float2*)&bias2[col];
                v0.x += b.x; v0.y += b.y; v1.x += b.x; v1.y += b.y;
            }
            *(float2*)&Cout[row * ldc + col] = v0;
            *(float2*)&Cout[(row + 8) * ldc + col] = v1;
        }
    }
}

// ======================= elementwise kernels =======================
__global__ void zero_misc_kernel() {
    long n = (long)B_ * K6H;
    for (long i = blockIdx.x * (long)blockDim.x + threadIdx.x; i < n; i += (long)gridDim.x * blockDim.x)
        g_Act[i] = __float2bfloat16(0.f);
    for (int i = blockIdx.x * blockDim.x + threadIdx.x; i < B_ * H_; i += gridDim.x * blockDim.x) {
        g_c0[i] = 0.f; g_c1[i] = 0.f;
    }
    for (int i = blockIdx.x * blockDim.x + threadIdx.x; i < H_ * (KX - 3 * F_); i += gridDim.x * blockDim.x) {
        int r = i / (KX - 3 * F_), c = i % (KX - 3 * F_);
        g_WbInp[(size_t)r * KX + 3 * F_ + c] = __float2bfloat16(0.f);
    }
}

__device__ __forceinline__ void split_bf16(float x, __nv_bfloat16& hi, __nv_bfloat16& lo) {
    hi = __float2bfloat16(x);
    lo = __float2bfloat16(x - __bfloat162float(hi));
}

// X[NBT,561] -> Xsplit[NBT,1728] = [hi | hi | lo | 0pad]
__global__ void split_X_kernel(const float* __restrict__ X) {
    long n = (long)NBT * KX;
    for (long i = blockIdx.x * (long)blockDim.x + threadIdx.x; i < n; i += (long)gridDim.x * blockDim.x) {
        long row = i / KX; int col = (int)(i % KX);
        if (col >= 3 * F_) { g_Xsplit[i] = __float2bfloat16(0.f); continue; }
        int seg = col / F_, k = col % F_;
        float x = X[row * F_ + k];
        __nv_bfloat16 hi, lo; split_bf16(x, hi, lo);
        g_Xsplit[i] = (seg == 2) ? lo : hi;
    }
}

// W[N,K] -> rows [hi | lo | hi] at out[r*ldout + off + {k, K+k, 2K+k}]
__global__ void split_W_kernel(const float* __restrict__ W, __nv_bfloat16* __restrict__ out,
                               int N, int K, long ldout, int off) {
    int n = N * K;
    for (int i = blockIdx.x * blockDim.x + threadIdx.x; i < n; i += gridDim.x * blockDim.x) {
        int r = i / K, k = i % K;
        __nv_bfloat16 hi, lo; split_bf16(W[i], hi, lo);
        __nv_bfloat16* o = out + (size_t)r * ldout + off;
        o[k] = hi; o[K + k] = lo; o[2 * K + k] = hi;
    }
}

// xp[NBT,256] -> Axp[NBT,768] = [hi | hi | lo]
__global__ void __launch_bounds__(256) split_xp_kernel() {
    long n = (long)NBT * H_;
    for (long i = blockIdx.x * (long)blockDim.x + threadIdx.x; i < n; i += (long)gridDim.x * blockDim.x) {
        long row = i >> 8; int j = (int)(i & 255);
        __nv_bfloat16 hi, lo; split_bf16(g_xp[i], hi, lo);
        __nv_bfloat16* o = g_Axp + row * K3H;
        o[j] = hi; o[j + 256] = hi; o[j + 512] = lo;
    }
}

__device__ __forceinline__ float sigmoidf_(float x) { return 1.0f / (1.0f + expf(-x)); }

__global__ void __launch_bounds__(256)
lstm_pw(const float* __restrict__ gates, float* __restrict__ c, int actOff,
        float* __restrict__ hs, int t, float* __restrict__ hn, float* __restrict__ cn)
{
    int idx = blockIdx.x * 256 + threadIdx.x;
    int b = idx >> 8, j = idx & 255;
    const float* g = gates + (size_t)b * G4H;
    float gi = g[j], gf = g[j + 256], gg = g[j + 512], go = g[j + 768];
    float c_new = sigmoidf_(gf) * c[idx] + sigmoidf_(gi) * tanhf(gg);
    float h_new = sigmoidf_(go) * tanhf(c_new);
    c[idx] = c_new;
    __nv_bfloat16 hi, lo; split_bf16(h_new, hi, lo);
    __nv_bfloat16* a = g_Act + (size_t)b * K6H + actOff;
    a[j] = hi; a[j + 256] = hi; a[j + 512] = lo;
    if (hs) hs[((size_t)b * T_ + t) * H_ + j] = h_new;
    if (hn) { hn[idx] = h_new; cn[idx] = c_new; }
}

__global__ void __launch_bounds__(256)
proj_kernel(const float* __restrict__ W_out, const float* __restrict__ b_out, float* __restrict__ out)
{
    __shared__ float Ws[O_ * H_];
    __shared__ float bs[O_];
    for (int i = threadIdx.x; i < O_ * H_; i += blockDim.x) Ws[i] = W_out[i];
    if (threadIdx.x < O_) bs[threadIdx.x] = b_out[threadIdx.x];
    __syncthreads();
    int warp = threadIdx.x / 32, lane = threadIdx.x % 32;
    long row = (long)blockIdx.x * 8 + warp;
    if (row >= NBT) return;
    float x[H_ / 32];
#pragma unroll
    for (int j = 0; j < H_ / 32; j++) x[j] = g_hs[row * H_ + lane + 32 * j];
#pragma unroll
    for (int o = 0; o < O_; o++) {
        float s = 0.f;
#pragma unroll
        for (int j = 0; j < H_ / 32; j++) s = fmaf(x[j], Ws[o * H_ + lane + 32 * j], s);
#pragma unroll
        for (int off = 16; off > 0; off >>= 1) s += __shfl_xor_sync(0xffffffffu, s, off);
        if (lane == 0) out[row * O_ + o] = s + bs[o];
    }
}

// ======================= launch =======================
extern "C" void kernel_launch(void* const* d_in, const int* in_sizes, int n_in,
                              void* d_out, int out_size)
{
    (void)in_sizes; (void)n_in; (void)out_size;
    const float* X     = (const float*)d_in[0];
    const float* W_inp = (const float*)d_in[1];
    const float* b_inp = (const float*)d_in[2];
    const float* Wih0  = (const float*)d_in[3];
    const float* Whh0  = (const float*)d_in[4];
    const float* bih0  = (const float*)d_in[5];
    const float* bhh0  = (const float*)d_in[6];
    const float* Wih1  = (const float*)d_in[7];
    const float* Whh1  = (const float*)d_in[8];
    const float* bih1  = (const float*)d_in[9];
    const float* bhh1  = (const float*)d_in[10];
    const float* W_out = (const float*)d_in[11];
    const float* b_out = (const float*)d_in[12];

    float* out     = (float*)d_out;
    float* hn_base = out + (size_t)B_ * T_ * O_;
    float* cn_base = hn_base + (size_t)2 * B_ * H_;

    static bool init = false;
    static __nv_bfloat16 *Xsplit, *Act, *Axp, *WbInp, *Wbih0p, *Wbhh0p, *Wb1p;
    static float *xp, *pre0, *gates, *c0, *c1, *hs;
    if (!init) {
        cudaGetSymbolAddress((void**)&Xsplit, g_Xsplit);
        cudaGetSymbolAddress((void**)&Axp,    g_Axp);
        cudaGetSymbolAddress((void**)&Act,    g_Act);
        cudaGetSymbolAddress((void**)&WbInp,  g_WbInp);
        cudaGetSymbolAddress((void**)&Wbih0p, g_Wbih0);
        cudaGetSymbolAddress((void**)&Wbhh0p, g_Wbhh0);
        cudaGetSymbolAddress((void**)&Wb1p,   g_Wb1);
        cudaGetSymbolAddress((void**)&xp,     g_xp);
        cudaGetSymbolAddress((void**)&pre0,   g_pre0);
        cudaGetSymbolAddress((void**)&gates,  g_gates);
        cudaGetSymbolAddress((void**)&c0,     g_c0);
        cudaGetSymbolAddress((void**)&c1,     g_c1);
        cudaGetSymbolAddress((void**)&hs,     g_hs);
        cudaFuncSetAttribute(tc_gemm, cudaFuncAttributeMaxDynamicSharedMemorySize, SM_TOTAL);
        init = true;
    }

    // 1) zero state + pads; split inputs/weights into bf16 hi/lo layouts
    zero_misc_kernel<<<1024, 256>>>();
    split_X_kernel<<<2048, 256>>>(X);
    split_W_kernel<<<256, 256>>>(W_inp, WbInp,  H_,  F_, KX,  0);
    split_W_kernel<<<256, 256>>>(Wih0,  Wbih0p, G4H, H_, K3H, 0);
    split_W_kernel<<<256, 256>>>(Whh0,  Wbhh0p, G4H, H_, K3H, 0);
    split_W_kernel<<<256, 256>>>(Wih1,  Wb1p,   G4H, H_, K6H, 0);
    split_W_kernel<<<256, 256>>>(Whh1,  Wb1p,   G4H, H_, K6H, K3H);

    // 2) xp = X @ W_inp^T + b_inp    [NBT, 256]
    {
        dim3 grid(H_ / TN_, NBT / TM_);   // (2, 640)
        tc_gemm<<<grid, 256, SM_TOTAL>>>(Xsplit, KX, WbInp, KX, KX,
                                         nullptr, 0, b_inp, nullptr, xp, H_);
    }
    split_xp_kernel<<<2048, 256>>>();

    // 3) pre0 = xp @ Wih0^T + bih0 + bhh0   [NBT, 1024]
    {
        dim3 grid(G4H / TN_, NBT / TM_);  // (8, 640)
        tc_gemm<<<grid, 256, SM_TOTAL>>>(Axp, K3H, Wbih0p, K3H, K3H,
                                         nullptr, 0, bih0, bhh0, pre0, G4H);
    }

    // 4) recurrence
    for (int t = 0; t < T_; t++) {
        bool last = (t == T_ - 1);
        dim3 grid(G4H / TN_, B_ / TM_);   // (8, 64)

        // layer0: gates = pre0[:, t, :] + h0 @ Whh0^T
        tc_gemm<<<grid, 256, SM_TOTAL>>>(Act, K6H, Wbhh0p, K3H, K3H,
                                         pre0 + (size_t)t * G4H, (long)T_ * G4H,
                                         nullptr, nullptr, gates, G4H);
        lstm_pw<<<(B_ * H_) / 256, 256>>>(gates, c0, 0, nullptr, t,
                                          last ? hn_base : nullptr,
                                          last ? cn_base : nullptr);

        // layer1: gates = bih1 + bhh1 + [h0 | h1] @ [Wih1 | Whh1]^T
        tc_gemm<<<grid, 256, SM_TOTAL>>>(Act, K6H, Wb1p, K6H, K6H,
                                         nullptr, 0, bih1, bhh1, gates, G4H);
        lstm_pw<<<(B_ * H_) / 256, 256>>>(gates, c1, K3H, hs, t,
                                          last ? hn_base + (size_t)B_ * H_ : nullptr,
                                          last ? cn_base + (size_t)B_ * H_ : nullptr);
    }

    // 5) outputs = hs @ W_out^T + b_out
    proj_kernel<<<NBT / 8, 256>>>(W_out, b_out, out);
}